// round 1
// baseline (speedup 1.0000x reference)
#include <cuda_runtime.h>
#include <math.h>

// Problem-size upper bounds (scratch sizing); runtime sizes derived from in_sizes.
#define NN 100000
#define EE 1600000
#define GG 2000
#define UU 128
#define SCAN_CHUNK 4096
#define NB_SCAN ((NN + SCAN_CHUNK - 1) / SCAN_CHUNK)   // 25

// ---------------- scratch (device globals; allocation-free) ----------------
__device__ float g_bufA[NN * UU];
__device__ float g_bufB[NN * UU];
__device__ float g_a9[NN * 9];
__device__ float g_dinv[NN];
__device__ int   g_deg[NN];
__device__ int   g_rowptr[NN + 1];
__device__ int   g_cursor[NN];
__device__ int   g_colsrc[EE];
__device__ float g_enorm[EE];
__device__ float g_score[NN];
__device__ float g_usum[GG];
__device__ float g_ucnt[GG];
__device__ float g_u[GG];
__device__ int   g_bsum[NB_SCAN];

// ---------------- init / degree ----------------
__global__ void k_zero(int n, int G) {
    int i = blockIdx.x * blockDim.x + threadIdx.x;
    if (i < n) g_deg[i] = 0;
    if (i < G) { g_usum[i] = 0.0f; g_ucnt[i] = 0.0f; }
}

__global__ void k_count_deg(const int* __restrict__ dst, int E) {
    int e = blockIdx.x * blockDim.x + threadIdx.x;
    if (e < E) atomicAdd(&g_deg[dst[e]], 1);
}

__global__ void k_dinv(int n) {
    int i = blockIdx.x * blockDim.x + threadIdx.x;
    if (i < n) g_dinv[i] = rsqrtf((float)g_deg[i] + 1.0f);
}

// ---------------- exclusive scan of g_deg -> g_rowptr ----------------
__global__ void k_scan_local(int n) {
    __shared__ int sh[256];
    int tid = threadIdx.x;
    int base = blockIdx.x * SCAN_CHUNK + tid * 16;
    int vals[16], loc[16];
    int s = 0;
    #pragma unroll
    for (int k = 0; k < 16; k++) {
        int idx = base + k;
        int v = (idx < n) ? g_deg[idx] : 0;
        vals[k] = v; loc[k] = s; s += v;
    }
    sh[tid] = s;
    __syncthreads();
    for (int off = 1; off < 256; off <<= 1) {
        int v = (tid >= off) ? sh[tid - off] : 0;
        __syncthreads();
        sh[tid] += v;
        __syncthreads();
    }
    int exoff = sh[tid] - s;  // exclusive prefix of this thread within block
    #pragma unroll
    for (int k = 0; k < 16; k++) {
        int idx = base + k;
        if (idx < n) g_rowptr[idx] = exoff + loc[k];
    }
    if (tid == 255) g_bsum[blockIdx.x] = sh[255];
    (void)vals;
}

__global__ void k_scan_bsum(int nb) {
    if (threadIdx.x == 0 && blockIdx.x == 0) {
        int run = 0;
        for (int b = 0; b < nb; b++) { int t = g_bsum[b]; g_bsum[b] = run; run += t; }
    }
}

__global__ void k_scan_add(int n, int E) {
    int i = blockIdx.x * blockDim.x + threadIdx.x;
    if (i < n) {
        int v = g_rowptr[i] + g_bsum[i / SCAN_CHUNK];
        g_rowptr[i] = v;
        g_cursor[i] = v;
    }
    if (i == 0) g_rowptr[n] = E;
}

__global__ void k_build_csr(const int* __restrict__ src, const int* __restrict__ dst, int E) {
    int e = blockIdx.x * blockDim.x + threadIdx.x;
    if (e < E) {
        int s = src[e], d = dst[e];
        int p = atomicAdd(&g_cursor[d], 1);
        g_colsrc[p] = s;
        g_enorm[p] = g_dinv[s] * g_dinv[d];
    }
}

// ---------------- aggregation ----------------
// a9[i][f] = sum_{e: dst=i} x[src][f]*enorm + x[i][f]*dinv[i]^2   (F = 9)
__global__ void k_agg9(const float* __restrict__ x, int n) {
    int w = (blockIdx.x * blockDim.x + threadIdx.x) >> 5;
    int lane = threadIdx.x & 31;
    if (w >= n || lane >= 9) return;
    float d = g_dinv[w];
    float acc = x[w * 9 + lane] * d * d;
    int beg = g_rowptr[w], end = g_rowptr[w + 1];
    for (int e = beg; e < end; e++) {
        int j = g_colsrc[e];
        float wt = g_enorm[e];
        acc += x[j * 9 + lane] * wt;
    }
    g_a9[w * 9 + lane] = acc;
}

// a[i][:] = sum_{e} h[src][:]*enorm + h[i][:]*dinv^2   (F = 128, warp/node, float4)
__global__ void k_agg128(const float* __restrict__ h, float* __restrict__ out, int n) {
    int w = (blockIdx.x * blockDim.x + threadIdx.x) >> 5;
    int lane = threadIdx.x & 31;
    if (w >= n) return;
    const float4* h4 = (const float4*)h;
    float d = g_dinv[w];
    float sn = d * d;
    float4 v = h4[w * 32 + lane];
    float4 acc; acc.x = v.x * sn; acc.y = v.y * sn; acc.z = v.z * sn; acc.w = v.w * sn;
    int beg = g_rowptr[w], end = g_rowptr[w + 1];
    for (int e = beg; e < end; e++) {
        int j = g_colsrc[e];
        float wt = g_enorm[e];
        float4 u = h4[j * 32 + lane];
        acc.x += u.x * wt; acc.y += u.y * wt; acc.z += u.z * wt; acc.w += u.w * wt;
    }
    ((float4*)out)[w * 32 + lane] = acc;
}

// ---------------- GEMMs ----------------
// out[i][:] = tanh(a9[i][0:9] @ W(9x128) + b)   warp/node
__global__ void k_gemm9(const float* __restrict__ W, const float* __restrict__ b,
                        float* __restrict__ out, int n) {
    int i = (blockIdx.x * blockDim.x + threadIdx.x) >> 5;
    int lane = threadIdx.x & 31;
    if (i >= n) return;
    float4 acc = ((const float4*)b)[lane];
    #pragma unroll
    for (int f = 0; f < 9; f++) {
        float a = g_a9[i * 9 + f];
        float4 w = ((const float4*)(W + f * 128))[lane];
        acc.x += a * w.x; acc.y += a * w.y; acc.z += a * w.z; acc.w += a * w.w;
    }
    acc.x = tanhf(acc.x); acc.y = tanhf(acc.y); acc.z = tanhf(acc.z); acc.w = tanhf(acc.w);
    ((float4*)out)[i * 32 + lane] = acc;
}

// C[n x 128] = A[n x 128] @ W[128 x 128] + bias, optional tanh.
// grid (ceil(n/64), 2): blockIdx.y selects 64-col half. 256 threads = 16x16,
// each thread computes a 4-node x 4-col register tile.
template <bool TANH>
__global__ void k_gemm128(const float* __restrict__ A, const float* __restrict__ W,
                          const float* __restrict__ bias, float* __restrict__ C, int n) {
    __shared__ float4 Ws4[128 * 16];   // [f][16 float4] = 64 cols per block
    __shared__ float bs[64];
    int tid = threadIdx.x;
    int c0 = blockIdx.y * 64;
    float* Ws = (float*)Ws4;
    for (int idx = tid; idx < 128 * 64; idx += 256) {
        int f = idx >> 6, c = idx & 63;
        Ws[idx] = W[f * 128 + c0 + c];
    }
    if (tid < 64) bs[tid] = bias[c0 + tid];
    __syncthreads();

    int tx = tid & 15, ty = tid >> 4;
    int m0 = blockIdx.x * 64 + ty * 4;
    float acc[4][4];
    #pragma unroll
    for (int j = 0; j < 4; j++)
        #pragma unroll
        for (int c = 0; c < 4; c++) acc[j][c] = 0.0f;

    int mi[4];
    #pragma unroll
    for (int j = 0; j < 4; j++) { int m = m0 + j; mi[j] = (m < n) ? m : 0; }

    const float4* A4 = (const float4*)A;
    #pragma unroll 4
    for (int f0 = 0; f0 < 128; f0 += 4) {
        float4 a[4], w[4];
        #pragma unroll
        for (int j = 0; j < 4; j++) a[j] = A4[mi[j] * 32 + (f0 >> 2)];
        #pragma unroll
        for (int k = 0; k < 4; k++) w[k] = Ws4[(f0 + k) * 16 + tx];
        #pragma unroll
        for (int j = 0; j < 4; j++) {
            acc[j][0] += a[j].x * w[0].x; acc[j][1] += a[j].x * w[0].y;
            acc[j][2] += a[j].x * w[0].z; acc[j][3] += a[j].x * w[0].w;
            acc[j][0] += a[j].y * w[1].x; acc[j][1] += a[j].y * w[1].y;
            acc[j][2] += a[j].y * w[1].z; acc[j][3] += a[j].y * w[1].w;
            acc[j][0] += a[j].z * w[2].x; acc[j][1] += a[j].z * w[2].y;
            acc[j][2] += a[j].z * w[2].z; acc[j][3] += a[j].z * w[2].w;
            acc[j][0] += a[j].w * w[3].x; acc[j][1] += a[j].w * w[3].y;
            acc[j][2] += a[j].w * w[3].z; acc[j][3] += a[j].w * w[3].w;
        }
    }

    #pragma unroll
    for (int j = 0; j < 4; j++) {
        int m = m0 + j;
        if (m < n) {
            float4 o;
            o.x = acc[j][0] + bs[tx * 4 + 0];
            o.y = acc[j][1] + bs[tx * 4 + 1];
            o.z = acc[j][2] + bs[tx * 4 + 2];
            o.w = acc[j][3] + bs[tx * 4 + 3];
            if (TANH) { o.x = tanhf(o.x); o.y = tanhf(o.y); o.z = tanhf(o.z); o.w = tanhf(o.w); }
            ((float4*)C)[m * 32 + (c0 >> 2) + tx] = o;
        }
    }
}

// ---------------- fused MLP head: t2 = tanh(h@Wf2+bf2); score = t2@Wf3+bf3 ----
// 256 threads = 8 nodes x 32 cols per block.
__global__ void k_head2(const float* __restrict__ h, const float* __restrict__ Wf2,
                        const float* __restrict__ bf2, const float* __restrict__ Wf3,
                        const float* __restrict__ bf3, int n) {
    __shared__ float w2s[128 * 32];
    __shared__ float rs[8 * 128];
    __shared__ float bf2s[32], wf3s[32];
    __shared__ float bf3s;
    int tid = threadIdx.x;
    for (int idx = tid; idx < 128 * 32; idx += 256) w2s[idx] = Wf2[idx];
    if (tid < 32) { bf2s[tid] = bf2[tid]; wf3s[tid] = Wf3[tid]; }
    if (tid == 0) bf3s = bf3[0];
    int nb = blockIdx.x * 8;
    for (int idx = tid; idx < 8 * 128; idx += 256) {
        int node = nb + (idx >> 7);
        int f = idx & 127;
        rs[idx] = (node < n) ? h[node * 128 + f] : 0.0f;
    }
    __syncthreads();

    int ln = tid >> 5, c = tid & 31;
    int node = nb + ln;
    const float4* rs4 = (const float4*)rs;
    float acc = 0.0f;
    #pragma unroll
    for (int f0 = 0; f0 < 128; f0 += 4) {
        float4 a = rs4[ln * 32 + (f0 >> 2)];
        acc += a.x * w2s[(f0 + 0) * 32 + c];
        acc += a.y * w2s[(f0 + 1) * 32 + c];
        acc += a.z * w2s[(f0 + 2) * 32 + c];
        acc += a.w * w2s[(f0 + 3) * 32 + c];
    }
    float t = tanhf(acc + bf2s[c]);
    float v = t * wf3s[c];
    #pragma unroll
    for (int off = 16; off > 0; off >>= 1) v += __shfl_xor_sync(0xffffffffu, v, off);
    if (c == 0 && node < n) g_score[node] = v + bf3s;
}

// ---------------- pooling + pairs ----------------
__global__ void k_pool_acc(const int* __restrict__ batch, int n) {
    int i = blockIdx.x * blockDim.x + threadIdx.x;
    if (i < n) {
        int g = batch[i];
        atomicAdd(&g_usum[g], g_score[i]);
        atomicAdd(&g_ucnt[g], 1.0f);
    }
}

__global__ void k_pool_fin(float* __restrict__ out, int P, int G) {
    int g = blockIdx.x * blockDim.x + threadIdx.x;
    if (g < G) {
        float u = g_usum[g] / fmaxf(g_ucnt[g], 1.0f);
        g_u[g] = u;
        out[P + g] = u;
    }
}

__global__ void k_pairs(const int* __restrict__ ia, const int* __restrict__ ib,
                        float* __restrict__ out, int P) {
    int p = blockIdx.x * blockDim.x + threadIdx.x;
    if (p < P) {
        float d = g_u[ib[p]] - g_u[ia[p]];
        out[p] = 1.0f / (1.0f + expf(-d));
    }
}

// ---------------- launch ----------------
extern "C" void kernel_launch(void* const* d_in, const int* in_sizes, int n_in,
                              void* d_out, int out_size) {
    const float* x     = (const float*)d_in[0];
    const int*   ei    = (const int*)d_in[1];
    const int*   batch = (const int*)d_in[2];
    const int*   ia    = (const int*)d_in[3];
    const int*   ib    = (const int*)d_in[4];
    const float* W_in  = (const float*)d_in[5];
    const float* b_in  = (const float*)d_in[6];
    const float* W1    = (const float*)d_in[7];
    const float* b1    = (const float*)d_in[8];
    const float* W2    = (const float*)d_in[9];
    const float* b2    = (const float*)d_in[10];
    const float* Wf1   = (const float*)d_in[11];
    const float* bf1   = (const float*)d_in[12];
    const float* Wf2   = (const float*)d_in[13];
    const float* bf2   = (const float*)d_in[14];
    const float* Wf3   = (const float*)d_in[15];
    const float* bf3   = (const float*)d_in[16];
    float* out = (float*)d_out;

    int n = in_sizes[0] / 9;
    int E = in_sizes[1] / 2;
    int P = in_sizes[3];
    int G = out_size - P;
    const int* src = ei;
    const int* dst = ei + E;

    int nb256  = (n + 255) / 256;
    int eb256  = (E + 255) / 256;
    int wb     = (n * 32 + 255) / 256;     // warp-per-node grids
    int scanNB = (n + SCAN_CHUNK - 1) / SCAN_CHUNK;

    // degree + dinv + CSR
    k_zero<<<nb256, 256>>>(n, G);
    k_count_deg<<<eb256, 256>>>(dst, E);
    k_dinv<<<nb256, 256>>>(n);
    k_scan_local<<<scanNB, 256>>>(n);
    k_scan_bsum<<<1, 32>>>(scanNB);
    k_scan_add<<<nb256, 256>>>(n, E);
    k_build_csr<<<eb256, 256>>>(src, dst, E);

    dim3 ggrid((n + 63) / 64, 2);

    // layer 1: aggregate raw 9-dim features, then GEMM 9->128 + tanh
    k_agg9<<<wb, 256>>>(x, n);
    k_gemm9<<<wb, 256>>>(W_in, b_in, g_bufA, n);

    // layer 2
    k_agg128<<<wb, 256>>>(g_bufA, g_bufB, n);
    k_gemm128<true><<<ggrid, 256>>>(g_bufB, W1, b1, g_bufA, n);

    // layer 3
    k_agg128<<<wb, 256>>>(g_bufA, g_bufB, n);
    k_gemm128<true><<<ggrid, 256>>>(g_bufB, W2, b2, g_bufA, n);

    // MLP: f1 (128->128 tanh), then fused f2+f3 head
    k_gemm128<true><<<ggrid, 256>>>(g_bufA, Wf1, bf1, g_bufB, n);
    k_head2<<<(n + 7) / 8, 256>>>(g_bufB, Wf2, bf2, Wf3, bf3, n);

    // pooling + pairwise sigmoid
    k_pool_acc<<<nb256, 256>>>(batch, n);
    k_pool_fin<<<(G + 255) / 256, 256>>>(out, P, G);
    k_pairs<<<(P + 255) / 256, 256>>>(ia, ib, out, P);
}

// round 2
// speedup vs baseline: 15.8767x; 15.8767x over previous
#include <cuda_runtime.h>
#include <math.h>

#define NN 100000
#define EE 1600000
#define GG 2000
#define NBLK 148
#define NTHR 512
#define NWARP (NBLK * NTHR / 32)

// ---------------- scratch (device globals; allocation-free) ----------------
__device__ float g_bufA[NN * 128];
__device__ float g_bufB[NN * 128];
__device__ float g_a9[NN * 9];
__device__ float g_dinv[NN];
__device__ int   g_deg[NN];
__device__ int   g_rowptr[NN + 1];
__device__ int   g_cursor[NN];
__device__ int   g_colsrc[EE];
__device__ float g_enorm[EE];
__device__ float g_usum[GG];
__device__ float g_ucnt[GG];
__device__ float g_u[GG];
__device__ int   g_part[NBLK];
__device__ unsigned long long g_arrive;          // cumulative arrivals (persists across replays)
__device__ volatile unsigned  g_release;         // cumulative completed rounds

// ---------------- packed fp32x2 helpers (sm_103a FFMA2) ----------------
__device__ __forceinline__ unsigned long long f2pack(float lo, float hi) {
    unsigned long long r;
    asm("mov.b64 %0, {%1, %2};" : "=l"(r) : "f"(lo), "f"(hi));
    return r;
}
__device__ __forceinline__ unsigned long long f2fma(unsigned long long a, unsigned long long b,
                                                    unsigned long long c) {
    unsigned long long d;
    asm("fma.rn.f32x2 %0, %1, %2, %3;" : "=l"(d) : "l"(a), "l"(b), "l"(c));
    return d;
}
__device__ __forceinline__ void f2unpack(unsigned long long v, float& lo, float& hi) {
    asm("mov.b64 {%0, %1}, %2;" : "=f"(lo), "=f"(hi) : "l"(v));
}

// ---------------- grid barrier (cumulative, replay-safe) ----------------
// All threads fence (orders own global stores; gpu-scope fence -> CCTL.IVALL so
// L1D never serves stale cross-SM data), thread 0 arrives + spins on release.
__device__ __forceinline__ void gsync(unsigned target) {
    __threadfence();
    __syncthreads();
    if (threadIdx.x == 0) {
        unsigned long long a = atomicAdd(&g_arrive, 1ULL) + 1ULL;
        if ((a % (unsigned long long)NBLK) == 0ULL)
            g_release = (unsigned)(a / (unsigned long long)NBLK);
        while (g_release < target) __nanosleep(128);
        __threadfence();
    }
    __syncthreads();
}

// ---------------- phase helpers ----------------
// GEMM: C[n x 128] = tanh(A[n x 128] @ W[128 x 128] + bias)
// 64-node x 128-col tile per block iteration; thread = 4 nodes x 4 cols; FFMA2 math.
__device__ __forceinline__ void gemm128_tanh(const float* __restrict__ A,
                                             const float* __restrict__ W,
                                             const float* __restrict__ bias,
                                             float* __restrict__ C, int n,
                                             float4* Ws4, float* bs) {
    const int tid = threadIdx.x;
    const float4* W4 = (const float4*)W;
    for (int i = tid; i < 128 * 32; i += NTHR) Ws4[i] = W4[i];
    if (tid < 128) bs[tid] = bias[tid];
    __syncthreads();

    const int tx = tid & 31;     // column group: cols 4tx..4tx+3
    const int ty = tid >> 5;     // node group:   nodes m0..m0+3
    const int ntile = (n + 63) >> 6;
    const float4* A4 = (const float4*)A;

    for (int t = blockIdx.x; t < ntile; t += NBLK) {
        const int m0 = t * 64 + ty * 4;
        int mi[4];
#pragma unroll
        for (int j = 0; j < 4; j++) { int m = m0 + j; mi[j] = (m < n) ? m : 0; }

        unsigned long long acc[4][2];
#pragma unroll
        for (int j = 0; j < 4; j++) { acc[j][0] = 0ULL; acc[j][1] = 0ULL; }

#pragma unroll 2
        for (int f = 0; f < 128; f += 4) {
            float4 w0 = Ws4[(f + 0) * 32 + tx];
            float4 w1 = Ws4[(f + 1) * 32 + tx];
            float4 w2 = Ws4[(f + 2) * 32 + tx];
            float4 w3 = Ws4[(f + 3) * 32 + tx];
            unsigned long long w0a = f2pack(w0.x, w0.y), w0b = f2pack(w0.z, w0.w);
            unsigned long long w1a = f2pack(w1.x, w1.y), w1b = f2pack(w1.z, w1.w);
            unsigned long long w2a = f2pack(w2.x, w2.y), w2b = f2pack(w2.z, w2.w);
            unsigned long long w3a = f2pack(w3.x, w3.y), w3b = f2pack(w3.z, w3.w);
#pragma unroll
            for (int j = 0; j < 4; j++) {
                float4 a = A4[mi[j] * 32 + (f >> 2)];
                unsigned long long t0 = f2pack(a.x, a.x);
                unsigned long long t1 = f2pack(a.y, a.y);
                unsigned long long t2 = f2pack(a.z, a.z);
                unsigned long long t3 = f2pack(a.w, a.w);
                acc[j][0] = f2fma(t0, w0a, acc[j][0]); acc[j][1] = f2fma(t0, w0b, acc[j][1]);
                acc[j][0] = f2fma(t1, w1a, acc[j][0]); acc[j][1] = f2fma(t1, w1b, acc[j][1]);
                acc[j][0] = f2fma(t2, w2a, acc[j][0]); acc[j][1] = f2fma(t2, w2b, acc[j][1]);
                acc[j][0] = f2fma(t3, w3a, acc[j][0]); acc[j][1] = f2fma(t3, w3b, acc[j][1]);
            }
        }

        float b0 = bs[tx * 4 + 0], b1 = bs[tx * 4 + 1];
        float b2 = bs[tx * 4 + 2], b3 = bs[tx * 4 + 3];
#pragma unroll
        for (int j = 0; j < 4; j++) {
            int m = m0 + j;
            if (m < n) {
                float o0, o1, o2, o3;
                f2unpack(acc[j][0], o0, o1);
                f2unpack(acc[j][1], o2, o3);
                float4 o;
                o.x = tanhf(o0 + b0); o.y = tanhf(o1 + b1);
                o.z = tanhf(o2 + b2); o.w = tanhf(o3 + b3);
                ((float4*)C)[m * 32 + tx] = o;
            }
        }
    }
}

// warp-per-node 128-wide gather-aggregate: out[i] = sum_e h[src]*enorm + h[i]*dinv^2
__device__ __forceinline__ void agg128(const float* __restrict__ h, float* __restrict__ out,
                                       int n) {
    int gw = (blockIdx.x * NTHR + threadIdx.x) >> 5;
    int lane = threadIdx.x & 31;
    const float4* h4 = (const float4*)h;
    for (int w = gw; w < n; w += NWARP) {
        float d = g_dinv[w];
        float sn = d * d;
        float4 v = h4[w * 32 + lane];
        float ax = v.x * sn, ay = v.y * sn, az = v.z * sn, aw = v.w * sn;
        int e = g_rowptr[w], end = g_rowptr[w + 1];
        for (; e + 4 <= end; e += 4) {
            int j0 = g_colsrc[e], j1 = g_colsrc[e + 1];
            int j2 = g_colsrc[e + 2], j3 = g_colsrc[e + 3];
            float e0 = g_enorm[e], e1 = g_enorm[e + 1];
            float e2 = g_enorm[e + 2], e3 = g_enorm[e + 3];
            float4 u0 = h4[j0 * 32 + lane];
            float4 u1 = h4[j1 * 32 + lane];
            float4 u2 = h4[j2 * 32 + lane];
            float4 u3 = h4[j3 * 32 + lane];
            ax += u0.x * e0; ay += u0.y * e0; az += u0.z * e0; aw += u0.w * e0;
            ax += u1.x * e1; ay += u1.y * e1; az += u1.z * e1; aw += u1.w * e1;
            ax += u2.x * e2; ay += u2.y * e2; az += u2.z * e2; aw += u2.w * e2;
            ax += u3.x * e3; ay += u3.y * e3; az += u3.z * e3; aw += u3.w * e3;
        }
        for (; e < end; e++) {
            int j = g_colsrc[e];
            float wt = g_enorm[e];
            float4 u = h4[j * 32 + lane];
            ax += u.x * wt; ay += u.y * wt; az += u.z * wt; aw += u.w * wt;
        }
        float4 o; o.x = ax; o.y = ay; o.z = az; o.w = aw;
        ((float4*)out)[w * 32 + lane] = o;
    }
}

// ---------------- the mega kernel ----------------
__global__ void __launch_bounds__(NTHR, 1)
mega(const float* __restrict__ x, const int* __restrict__ ei, const int* __restrict__ batch,
     const int* __restrict__ ia, const int* __restrict__ ib,
     const float* __restrict__ W_in, const float* __restrict__ b_in,
     const float* __restrict__ W1, const float* __restrict__ b1,
     const float* __restrict__ W2, const float* __restrict__ b2,
     const float* __restrict__ Wf1, const float* __restrict__ bf1,
     const float* __restrict__ Wf2, const float* __restrict__ bf2,
     const float* __restrict__ Wf3, const float* __restrict__ bf3,
     float* __restrict__ out, int n, int E, int P, int G) {
    extern __shared__ unsigned char smraw[];
    float4* Ws4 = (float4*)smraw;                       // up to 64 KB weight stage
    float*  bs  = (float*)(smraw + 65536);              // bias / small params
    int*    sci = (int*)(smraw + 65536);                // scan scratch (phase-disjoint)

    const int tid = threadIdx.x;
    const int bid = blockIdx.x;
    const int gt  = bid * NTHR + tid;
    const int GSTRIDE = NBLK * NTHR;
    const int lane = tid & 31;
    const int gw = gt >> 5;
    const int* src = ei;
    const int* dst = ei + E;

    __shared__ unsigned s_base;
    if (tid == 0) s_base = g_release;   // stable: no round can complete before every block reads
    __syncthreads();
    const unsigned base = s_base;
    unsigned rnd = 0;

    // ---- P0: zero ----
    for (int i = gt; i < n; i += GSTRIDE) g_deg[i] = 0;
    if (gt < G) { g_usum[gt] = 0.0f; g_ucnt[gt] = 0.0f; }
    gsync(base + ++rnd);

    // ---- P1: in-degree count ----
    for (int e = gt; e < E; e += GSTRIDE) atomicAdd(&g_deg[dst[e]], 1);
    gsync(base + ++rnd);

    // ---- P2: block-local scan of deg -> rowptr (local excl), dinv, partials ----
    {
        const int CH = (n + NBLK - 1) / NBLK;           // <= 2*NTHR
        const int bbase = bid * CH;
        const int lim = (bbase + CH < n) ? bbase + CH : n;
        int i0 = bbase + 2 * tid, i1 = i0 + 1;
        int v0 = (i0 < lim) ? g_deg[i0] : 0;
        int v1 = (i1 < lim) ? g_deg[i1] : 0;
        if (i0 < lim) g_dinv[i0] = rsqrtf((float)v0 + 1.0f);
        if (i1 < lim) g_dinv[i1] = rsqrtf((float)v1 + 1.0f);
        int s = v0 + v1;
        sci[tid] = s;
        __syncthreads();
        for (int off = 1; off < NTHR; off <<= 1) {
            int t_ = (tid >= off) ? sci[tid - off] : 0;
            __syncthreads();
            sci[tid] += t_;
            __syncthreads();
        }
        int exc = sci[tid] - s;
        if (i0 < lim) g_rowptr[i0] = exc;
        if (i1 < lim) g_rowptr[i1] = exc + v0;
        if (tid == NTHR - 1) g_part[bid] = sci[NTHR - 1];
    }
    gsync(base + ++rnd);

    // ---- P3: block 0 scans the 148 partials ----
    if (bid == 0) {
        int v = (tid < NBLK) ? g_part[tid] : 0;
        sci[tid] = v;
        __syncthreads();
        for (int off = 1; off < 256; off <<= 1) {
            int t_ = (tid >= off && tid < 256) ? sci[tid - off] : 0;
            __syncthreads();
            if (tid < 256) sci[tid] += t_;
            __syncthreads();
        }
        if (tid < NBLK) g_part[tid] = sci[tid] - v;     // exclusive
    }
    gsync(base + ++rnd);

    // ---- P4: globalize rowptr + init cursor ----
    {
        const int CH = (n + NBLK - 1) / NBLK;
        const int bbase = bid * CH;
        const int lim = (bbase + CH < n) ? bbase + CH : n;
        const int off = g_part[bid];
        int i0 = bbase + 2 * tid, i1 = i0 + 1;
        if (i0 < lim) { int v = g_rowptr[i0] + off; g_rowptr[i0] = v; g_cursor[i0] = v; }
        if (i1 < lim) { int v = g_rowptr[i1] + off; g_rowptr[i1] = v; g_cursor[i1] = v; }
        if (gt == 0) g_rowptr[n] = E;
    }
    gsync(base + ++rnd);

    // ---- P5: build CSR ----
    for (int e = gt; e < E; e += GSTRIDE) {
        int s = src[e], d = dst[e];
        int p = atomicAdd(&g_cursor[d], 1);
        g_colsrc[p] = s;
        g_enorm[p] = g_dinv[s] * g_dinv[d];
    }
    gsync(base + ++rnd);

    // ---- P6: aggregate raw 9-dim features ----
    for (int w = gw; w < n; w += NWARP) {
        if (lane < 9) {
            float d = g_dinv[w];
            float acc = x[w * 9 + lane] * d * d;
            int e = g_rowptr[w], end = g_rowptr[w + 1];
            for (; e < end; e++) {
                int j = g_colsrc[e];
                acc += x[j * 9 + lane] * g_enorm[e];
            }
            g_a9[w * 9 + lane] = acc;
        }
    }
    gsync(base + ++rnd);

    // ---- P7: 9->128 GEMM + tanh -> bufA ----
    {
        const float4* W4 = (const float4*)W_in;         // 9*32 float4
        for (int i = tid; i < 9 * 32; i += NTHR) Ws4[i] = W4[i];
        if (tid < 128) bs[tid] = b_in[tid];
        __syncthreads();
        for (int w = gw; w < n; w += NWARP) {
            float4 acc = ((const float4*)bs)[lane];
#pragma unroll
            for (int f = 0; f < 9; f++) {
                float a = g_a9[w * 9 + f];
                float4 wv = Ws4[f * 32 + lane];
                acc.x += a * wv.x; acc.y += a * wv.y;
                acc.z += a * wv.z; acc.w += a * wv.w;
            }
            acc.x = tanhf(acc.x); acc.y = tanhf(acc.y);
            acc.z = tanhf(acc.z); acc.w = tanhf(acc.w);
            ((float4*)g_bufA)[w * 32 + lane] = acc;
        }
    }
    gsync(base + ++rnd);

    // ---- P8..P12: two GCN layers + Wf1 ----
    agg128(g_bufA, g_bufB, n);
    gsync(base + ++rnd);
    gemm128_tanh(g_bufB, W1, b1, g_bufA, n, Ws4, bs);
    gsync(base + ++rnd);
    agg128(g_bufA, g_bufB, n);
    gsync(base + ++rnd);
    gemm128_tanh(g_bufB, W2, b2, g_bufA, n, Ws4, bs);
    gsync(base + ++rnd);
    gemm128_tanh(g_bufA, Wf1, bf1, g_bufB, n, Ws4, bs);
    gsync(base + ++rnd);

    // ---- P13: fused head (Wf2 tanh, Wf3 dot) + pooled atomics ----
    {
        float* W2s = (float*)smraw;                     // 128*32 floats = 16 KB
        for (int i = tid; i < 128 * 32; i += NTHR) W2s[i] = Wf2[i];
        if (tid < 32) { bs[tid] = bf2[tid]; bs[32 + tid] = Wf3[tid]; }
        if (tid == 0) bs[64] = bf3[0];
        __syncthreads();
        for (int w = gw; w < n; w += NWARP) {
            const float4* hp = (const float4*)(g_bufB + w * 128);
            float acc = 0.0f;
#pragma unroll 8
            for (int f0 = 0; f0 < 128; f0 += 4) {
                float4 a = hp[f0 >> 2];
                acc += a.x * W2s[(f0 + 0) * 32 + lane];
                acc += a.y * W2s[(f0 + 1) * 32 + lane];
                acc += a.z * W2s[(f0 + 2) * 32 + lane];
                acc += a.w * W2s[(f0 + 3) * 32 + lane];
            }
            float t = tanhf(acc + bs[lane]);
            float v = t * bs[32 + lane];
#pragma unroll
            for (int off = 16; off > 0; off >>= 1)
                v += __shfl_xor_sync(0xffffffffu, v, off);
            if (lane == 0) {
                float s = v + bs[64];
                int g = batch[w];
                atomicAdd(&g_usum[g], s);
                atomicAdd(&g_ucnt[g], 1.0f);
            }
        }
    }
    gsync(base + ++rnd);

    // ---- P14: finalize util ----
    if (gt < G) {
        float u = g_usum[gt] / fmaxf(g_ucnt[gt], 1.0f);
        g_u[gt] = u;
        out[P + gt] = u;
    }
    gsync(base + ++rnd);

    // ---- P15: pairwise sigmoid ----
    if (gt < P) {
        float d = g_u[ib[gt]] - g_u[ia[gt]];
        out[gt] = 1.0f / (1.0f + expf(-d));
    }
}

// ---------------- launch ----------------
extern "C" void kernel_launch(void* const* d_in, const int* in_sizes, int n_in,
                              void* d_out, int out_size) {
    const float* x     = (const float*)d_in[0];
    const int*   ei    = (const int*)d_in[1];
    const int*   batch = (const int*)d_in[2];
    const int*   ia    = (const int*)d_in[3];
    const int*   ib    = (const int*)d_in[4];
    const float* W_in  = (const float*)d_in[5];
    const float* b_in  = (const float*)d_in[6];
    const float* W1    = (const float*)d_in[7];
    const float* b1    = (const float*)d_in[8];
    const float* W2    = (const float*)d_in[9];
    const float* b2    = (const float*)d_in[10];
    const float* Wf1   = (const float*)d_in[11];
    const float* bf1   = (const float*)d_in[12];
    const float* Wf2   = (const float*)d_in[13];
    const float* bf2   = (const float*)d_in[14];
    const float* Wf3   = (const float*)d_in[15];
    const float* bf3   = (const float*)d_in[16];
    float* out = (float*)d_out;

    int n = in_sizes[0] / 9;
    int E = in_sizes[1] / 2;
    int P = in_sizes[3];
    int G = out_size - P;

    static int smem_set = 0;
    (void)smem_set;
    cudaFuncSetAttribute(mega, cudaFuncAttributeMaxDynamicSharedMemorySize, 67584);

    mega<<<NBLK, NTHR, 67584>>>(x, ei, batch, ia, ib, W_in, b_in, W1, b1, W2, b2,
                                Wf1, bf1, Wf2, bf2, Wf3, bf3, out, n, E, P, G);
}